// round 9
// baseline (speedup 1.0000x reference)
#include <cuda_runtime.h>
#include <math.h>
#include <stdint.h>

#define Bn 4
#define Hn 8
#define Nn 4096
#define Dn 64
#define Mn 256
#define NHEAD (Bn*Hn)
#define NSPLIT 16

// ---- scratch (device globals: no allocation allowed in kernel_launch) ----
static __device__ float        g_KP[(size_t)NHEAD*Nn*Mn];   // 134 MB projected-K
static __device__ float        g_QP[(size_t)NHEAD*Nn*Mn];   // 134 MB phi_q (unscaled)
static __device__ float        g_diag[NHEAD*Nn];
static __device__ float        g_dinv[NHEAD*Nn];
static __device__ unsigned int g_stab[NHEAD];
static __device__ float        g_ctx[NHEAD*Mn*Dn];
static __device__ float        g_ksum[NHEAD*Mn];

typedef unsigned long long ull;

__device__ __forceinline__ ull pk2(float x){
    ull r;
    asm("mov.b64 %0, {%1, %1};" : "=l"(r) : "r"(__float_as_uint(x)));
    return r;
}
__device__ __forceinline__ void fma2(ull &c, ull a, ull b){
    asm("fma.rn.f32x2 %0, %1, %2, %0;" : "+l"(c) : "l"(a), "l"(b));
}
__device__ __forceinline__ float2 up2(ull v){
    unsigned lo, hi;
    asm("mov.b64 {%0, %1}, %2;" : "=r"(lo), "=r"(hi) : "l"(v));
    return make_float2(__uint_as_float(lo), __uint_as_float(hi));
}
__device__ __forceinline__ unsigned f2ord(float f){
    unsigned u = __float_as_uint(f);
    return (u & 0x80000000u) ? ~u : (u | 0x80000000u);
}
__device__ __forceinline__ float ord2f(unsigned u){
    return __uint_as_float((u & 0x80000000u) ? (u ^ 0x80000000u) : ~u);
}

__global__ void k_init(){
    int idx = blockIdx.x*blockDim.x + threadIdx.x;
    if (idx < NHEAD*Mn*Dn) g_ctx[idx]  = 0.f;
    if (idx < NHEAD*Mn)    g_ksum[idx] = 0.f;
    if (idx < NHEAD)       g_stab[idx] = 0u;
}

// ---------------------------------------------------------------------------
// Kernel A: KP = (K*scale*mask) @ proj^T per head; diag_k; per-head max.
// grid (Nn/64, NHEAD), 256 threads.
// smem: sA2 = 64x64 duplicated pairs (32KB), sPt = [d][m] fp32 (64KB)
// thread (nt=warp, mt=lane): rows nt+8i (i<8), m in {4mt..4mt+3} u {128+4mt..}
// ---------------------------------------------------------------------------
__global__ __launch_bounds__(256,2) void k_projK(const float* __restrict__ Kp,
                                                 const float* __restrict__ mask,
                                                 const float* __restrict__ proj){
    extern __shared__ float sm[];
    ull*   sA2 = reinterpret_cast<ull*>(sm);   // 64*64 pairs
    float* sPt = sm + 64*64*2;                 // 64 x 256
    __shared__ float sred[8];

    const int head = blockIdx.y;
    const int bIdx = head / Hn;
    const int n0   = blockIdx.x * 64;
    const int tid  = threadIdx.x;
    const float scale = 0.35355339059327373f;

    for (int i = tid; i < 64*64; i += 256){
        int r = i >> 6, d = i & 63;
        float mv = mask[bIdx*Nn + n0 + r];
        float v  = Kp[((size_t)head*Nn + n0 + r)*Dn + d] * (scale*mv);
        sA2[r*64 + d] = pk2(v);
    }
    for (int i = tid; i < Mn*16; i += 256){
        int m = i >> 4, dq = i & 15;
        float4 p = reinterpret_cast<const float4*>(proj)[m*16 + dq];
        sPt[(dq*4+0)*Mn + m] = p.x;
        sPt[(dq*4+1)*Mn + m] = p.y;
        sPt[(dq*4+2)*Mn + m] = p.z;
        sPt[(dq*4+3)*Mn + m] = p.w;
    }
    __syncthreads();

    const int mt = tid & 31, nt = tid >> 5;
    ull acc[8][4];
    #pragma unroll
    for (int i=0;i<8;i++)
        #pragma unroll
        for (int u=0;u<4;u++) acc[i][u] = 0ull;

    #pragma unroll 4
    for (int d = 0; d < 64; d++){
        ull a2[8], b2[4];
        #pragma unroll
        for (int i=0;i<8;i++) a2[i] = sA2[(nt+8*i)*64 + d];
        #pragma unroll
        for (int j=0;j<2;j++){
            ulonglong2 t = *reinterpret_cast<const ulonglong2*>(&sPt[d*Mn + j*128 + 4*mt]);
            b2[2*j] = t.x; b2[2*j+1] = t.y;
        }
        #pragma unroll
        for (int i=0;i<8;i++)
            #pragma unroll
            for (int u=0;u<4;u++) fma2(acc[i][u], a2[i], b2[u]);
    }

    float lmax = -3.4e38f;
    #pragma unroll
    for (int i=0;i<8;i++){
        size_t base = ((size_t)head*Nn + n0 + nt + 8*i)*Mn;
        #pragma unroll
        for (int j=0;j<2;j++){
            float2 v0 = up2(acc[i][2*j]);
            float2 v1 = up2(acc[i][2*j+1]);
            *reinterpret_cast<float4*>(&g_KP[base + j*128 + 4*mt]) =
                make_float4(v0.x, v0.y, v1.x, v1.y);
            lmax = fmaxf(lmax, fmaxf(fmaxf(v0.x,v0.y), fmaxf(v1.x,v1.y)));
        }
    }
    #pragma unroll
    for (int off=16; off>0; off>>=1)
        lmax = fmaxf(lmax, __shfl_xor_sync(0xffffffffu, lmax, off));
    if (mt == 0) sred[nt] = lmax;
    __syncthreads();

    if (tid < 64){
        float s = 0.f;
        #pragma unroll 8
        for (int d=0; d<64; d++){
            float v = up2(sA2[tid*64 + d]).x;
            s = fmaf(v, v, s);
        }
        g_diag[head*Nn + n0 + tid] = 0.5f*s;
    }
    if (tid == 0){
        float m2 = sred[0];
        #pragma unroll
        for (int w=1; w<8; w++) m2 = fmaxf(m2, sred[w]);
        atomicMax(&g_stab[head], f2ord(m2));
    }
}

// ---------------------------------------------------------------------------
// Kernel C: phi_k = ratio*(exp(KP - diag - stab)+eps);
//           ksum += sum_n phi_k; ctx[m][e] += sum_n phi_k[n][m]*v[n][e]
// grid (16 splits, NHEAD), 256 threads.
// thread: m in {4mg..4mg+3} u {128+4mg..} (4 pairs), e = 8eg..8eg+7
// ---------------------------------------------------------------------------
__global__ __launch_bounds__(256,2) void k_ctx(const float* __restrict__ V,
                                               const float* __restrict__ mask){
    extern __shared__ float sm[];
    float* sPhi  = sm;                                   // 16 x 256
    ull*   sV2   = reinterpret_cast<ull*>(sm + 16*256);  // 16 x 64 pairs (8KB)
    float* sDiag = sm + 16*256 + 16*64*2;                // 16

    const int head  = blockIdx.y;
    const int bIdx  = head / Hn;
    const int nbase0= blockIdx.x * (Nn/NSPLIT);
    const int tid   = threadIdx.x;
    const float stab = ord2f(g_stab[head]);
    const float ratio = 0.0625f, eps = 1e-4f;
    const int mg = tid & 31, eg = tid >> 5;

    ull acc[4][8];
    #pragma unroll
    for (int u=0;u<4;u++)
        #pragma unroll
        for (int t=0;t<8;t++) acc[u][t] = 0ull;
    float ak = 0.f;

    for (int nb = nbase0; nb < nbase0 + Nn/NSPLIT; nb += 16){
        if (tid < 16) sDiag[tid] = g_diag[head*Nn + nb + tid];
        for (int i = tid; i < 16*64; i += 256){
            int r = i >> 6;
            float v = V[((size_t)head*Nn + nb + r)*Dn + (i & 63)]
                    * mask[bIdx*Nn + nb + r];
            sV2[i] = pk2(v);
        }
        __syncthreads();

        const float* kpBase = &g_KP[((size_t)head*Nn + nb)*Mn + tid];
        #pragma unroll
        for (int s=0; s<16; s++){
            float xp = kpBase[(size_t)s*Mn];
            float ph = ratio*(__expf(xp - sDiag[s] - stab) + eps);
            sPhi[s*256 + tid] = ph;
            ak += ph;
        }
        __syncthreads();

        #pragma unroll 2
        for (int s=0; s<16; s++){
            ull a2[4], b2[8];
            #pragma unroll
            for (int j=0;j<2;j++){
                ulonglong2 t = *reinterpret_cast<const ulonglong2*>(
                    &sPhi[s*256 + j*128 + 4*mg]);
                a2[2*j] = t.x; a2[2*j+1] = t.y;
            }
            #pragma unroll
            for (int t=0;t<8;t++) b2[t] = sV2[s*64 + 8*eg + t];
            #pragma unroll
            for (int u=0;u<4;u++)
                #pragma unroll
                for (int t=0;t<8;t++) fma2(acc[u][t], a2[u], b2[t]);
        }
        __syncthreads();
    }

    atomicAdd(&g_ksum[head*Mn + tid], ak);
    #pragma unroll
    for (int u=0;u<4;u++){
        int m0 = (u>>1)*128 + 4*mg + (u&1)*2;
        #pragma unroll
        for (int t=0;t<8;t++){
            float2 v = up2(acc[u][t]);
            atomicAdd(&g_ctx[((size_t)head*Mn + m0    )*Dn + 8*eg + t], v.x);
            atomicAdd(&g_ctx[((size_t)head*Mn + m0 + 1)*Dn + 8*eg + t], v.y);
        }
    }
}

// ---------------------------------------------------------------------------
// Kernel Q: QP GEMM -> rowmax -> phi_q (unscaled) -> g_QP; Dinv -> g_dinv.
// grid (Nn/64, NHEAD), 256 threads. Same mapping as k_projK.
// ---------------------------------------------------------------------------
__global__ __launch_bounds__(256,2) void k_qphi(const float* __restrict__ Qp,
                                                const float* __restrict__ proj){
    extern __shared__ float sm[];
    ull*   sA2 = reinterpret_cast<ull*>(sm);   // 64*64 pairs
    float* sPt = sm + 64*64*2;                 // 64 x 256
    float* sKs = sPt + 64*256;                 // 256
    __shared__ float sDg[64];

    const int head = blockIdx.y;
    const int n0   = blockIdx.x * 64;
    const int tid  = threadIdx.x;
    const float scale = 0.35355339059327373f;
    const float ratio = 0.0625f, eps = 1e-4f;

    sKs[tid] = g_ksum[head*Mn + tid];
    for (int i = tid; i < 64*64; i += 256){
        int r = i >> 6, d = i & 63;
        float v = Qp[((size_t)head*Nn + n0 + r)*Dn + d] * scale;
        sA2[r*64 + d] = pk2(v);
    }
    for (int i = tid; i < Mn*16; i += 256){
        int m = i >> 4, dq = i & 15;
        float4 p = reinterpret_cast<const float4*>(proj)[m*16 + dq];
        sPt[(dq*4+0)*Mn + m] = p.x;
        sPt[(dq*4+1)*Mn + m] = p.y;
        sPt[(dq*4+2)*Mn + m] = p.z;
        sPt[(dq*4+3)*Mn + m] = p.w;
    }
    __syncthreads();
    if (tid < 64){
        float s = 0.f;
        #pragma unroll 8
        for (int d=0; d<64; d++){
            float v = up2(sA2[tid*64 + d]).x;
            s = fmaf(v, v, s);
        }
        sDg[tid] = 0.5f*s;
    }
    __syncthreads();

    const int mt = tid & 31, nt = tid >> 5;
    ull acc[8][4];
    #pragma unroll
    for (int i=0;i<8;i++)
        #pragma unroll
        for (int u=0;u<4;u++) acc[i][u] = 0ull;

    #pragma unroll 4
    for (int d = 0; d < 64; d++){
        ull a2[8], b2[4];
        #pragma unroll
        for (int i=0;i<8;i++) a2[i] = sA2[(nt+8*i)*64 + d];
        #pragma unroll
        for (int j=0;j<2;j++){
            ulonglong2 t = *reinterpret_cast<const ulonglong2*>(&sPt[d*Mn + j*128 + 4*mt]);
            b2[2*j] = t.x; b2[2*j+1] = t.y;
        }
        #pragma unroll
        for (int i=0;i<8;i++)
            #pragma unroll
            for (int u=0;u<4;u++) fma2(acc[i][u], a2[i], b2[u]);
    }

    // per row: rowmax over 256 m (8 local + warp shfl), phi, D
    #pragma unroll
    for (int i=0;i<8;i++){
        float x[8];
        #pragma unroll
        for (int u=0;u<4;u++){
            float2 v = up2(acc[i][u]);
            x[2*u] = v.x; x[2*u+1] = v.y;
        }
        float rm = x[0];
        #pragma unroll
        for (int j=1;j<8;j++) rm = fmaxf(rm, x[j]);
        #pragma unroll
        for (int off=16; off>0; off>>=1)
            rm = fmaxf(rm, __shfl_xor_sync(0xffffffffu, rm, off));
        float dg = sDg[nt + 8*i];
        float ds = 0.f;
        float ph[8];
        #pragma unroll
        for (int u=0;u<4;u++){
            int m0 = (u>>1)*128 + 4*mt + (u&1)*2;
            ph[2*u]   = ratio*(__expf(x[2*u]   - dg - rm) + eps);
            ph[2*u+1] = ratio*(__expf(x[2*u+1] - dg - rm) + eps);
            ds = fmaf(ph[2*u],   sKs[m0],   ds);
            ds = fmaf(ph[2*u+1], sKs[m0+1], ds);
        }
        #pragma unroll
        for (int off=16; off>0; off>>=1)
            ds += __shfl_xor_sync(0xffffffffu, ds, off);
        size_t base = ((size_t)head*Nn + n0 + nt + 8*i)*Mn;
        *reinterpret_cast<float4*>(&g_QP[base + 4*mt]) =
            make_float4(ph[0], ph[1], ph[2], ph[3]);
        *reinterpret_cast<float4*>(&g_QP[base + 128 + 4*mt]) =
            make_float4(ph[4], ph[5], ph[6], ph[7]);
        if (mt == (nt + 8*i) % 32 && 0) {} // no-op
        // one lane per row writes dinv (lane mt==0 has full ds after butterfly)
        if (mt == 0) g_dinv[head*Nn + n0 + nt + 8*i] = 1.f/ds;
    }
}

// ---------------------------------------------------------------------------
// Kernel O: out = (phi @ ctx) * Dinv per row. K=256 in chunks of 16 m.
// grid (Nn/256, NHEAD), 256 threads.
// smem: sCtx 256x64 f (64KB) + sP2 256x16 pairs (32KB)
// thread: rows 8rg..8rg+7, e = 8eg..8eg+7
// ---------------------------------------------------------------------------
__global__ __launch_bounds__(256,2) void k_out2(float* __restrict__ outp){
    extern __shared__ float sm[];
    float* sCtx = sm;                                   // 256 x 64
    ull*   sP2  = reinterpret_cast<ull*>(sm + 256*64);  // 256 x 16 pairs

    const int head = blockIdx.y;
    const int n0   = blockIdx.x * 256;
    const int tid  = threadIdx.x;
    const int rg = tid >> 3;     // 0..31
    const int eg = tid & 7;      // 0..7

    for (int i = tid; i < Mn*Dn/4; i += 256)
        reinterpret_cast<float4*>(sCtx)[i] =
            reinterpret_cast<const float4*>(&g_ctx[(size_t)head*Mn*Dn])[i];

    float dv[8];
    #pragma unroll
    for (int i=0;i<8;i++) dv[i] = g_dinv[head*Nn + n0 + 8*rg + i];

    ull acc[8][4];
    #pragma unroll
    for (int i=0;i<8;i++)
        #pragma unroll
        for (int u=0;u<4;u++) acc[i][u] = 0ull;

    for (int m0 = 0; m0 < Mn; m0 += 16){
        __syncthreads();
        // load phi chunk [256 rows][16 m] and store duplicated pairs
        #pragma unroll
        for (int q = 0; q < 4; q++){
            int idx = tid + q*256;           // 1024 float4 total
            int r = idx >> 2, mq = idx & 3;
            float4 v = *reinterpret_cast<const float4*>(
                &g_QP[((size_t)head*Nn + n0 + r)*Mn + m0 + 4*mq]);
            ull* dst = &sP2[r*16 + 4*mq];
            dst[0] = pk2(v.x); dst[1] = pk2(v.y);
            dst[2] = pk2(v.z); dst[3] = pk2(v.w);
        }
        __syncthreads();

        #pragma unroll 4
        for (int m = 0; m < 16; m++){
            ull a2[8], b2[4];
            #pragma unroll
            for (int i=0;i<8;i++) a2[i] = sP2[(8*rg+i)*16 + m];
            #pragma unroll
            for (int j=0;j<2;j++){
                ulonglong2 t = *reinterpret_cast<const ulonglong2*>(
                    &sCtx[(m0+m)*Dn + 8*eg + 4*j]);
                b2[2*j] = t.x; b2[2*j+1] = t.y;
            }
            #pragma unroll
            for (int i=0;i<8;i++)
                #pragma unroll
                for (int u=0;u<4;u++) fma2(acc[i][u], a2[i], b2[u]);
        }
    }

    #pragma unroll
    for (int i=0;i<8;i++){
        size_t base = ((size_t)head*Nn + n0 + 8*rg + i)*Dn + 8*eg;
        float2 v0 = up2(acc[i][0]), v1 = up2(acc[i][1]);
        float2 v2 = up2(acc[i][2]), v3 = up2(acc[i][3]);
        *reinterpret_cast<float4*>(&outp[base]) =
            make_float4(v0.x*dv[i], v0.y*dv[i], v1.x*dv[i], v1.y*dv[i]);
        *reinterpret_cast<float4*>(&outp[base+4]) =
            make_float4(v2.x*dv[i], v2.y*dv[i], v3.x*dv[i], v3.y*dv[i]);
    }
}

// ---------------------------------------------------------------------------
extern "C" void kernel_launch(void* const* d_in, const int* in_sizes, int n_in,
                              void* d_out, int out_size) {
    const float* Q    = (const float*)d_in[0];
    const float* K    = (const float*)d_in[1];
    const float* V    = (const float*)d_in[2];
    const float* mask = (const float*)d_in[3];
    const float* proj = (const float*)d_in[4];
    float* out        = (float*)d_out;

    const int smA = (64*64*2 + 64*256) * 4;              // 98304
    const int smC = (16*256 + 16*64*2 + 16) * 4;         // 24640
    const int smQ = (64*64*2 + 64*256 + 256) * 4;        // 99328
    const int smO = (256*64 + 256*16*2) * 4;             // 98304

    cudaFuncSetAttribute(k_projK, cudaFuncAttributeMaxDynamicSharedMemorySize, smA);
    cudaFuncSetAttribute(k_qphi,  cudaFuncAttributeMaxDynamicSharedMemorySize, smQ);
    cudaFuncSetAttribute(k_out2,  cudaFuncAttributeMaxDynamicSharedMemorySize, smO);

    k_init <<<(NHEAD*Mn*Dn + 255)/256, 256>>>();
    k_projK<<<dim3(Nn/64,  NHEAD), 256, smA>>>(K, mask, proj);
    k_ctx  <<<dim3(NSPLIT, NHEAD), 256, smC>>>(V, mask);
    k_qphi <<<dim3(Nn/64,  NHEAD), 256, smQ>>>(Q, proj);
    k_out2 <<<dim3(Nn/256, NHEAD), 256, smO>>>(out);
}